// round 14
// baseline (speedup 1.0000x reference)
#include <cuda_runtime.h>
#include <cuda_fp16.h>
#include <cstdint>

// Problem constants
#define BSZ   64
#define PP    512
#define DWM   1024
#define WIN   128
#define MROWS (BSZ * PP)   // 32768
#define TQ    8

// 16-byte vector of 8 halves for single-STG.128 stores
struct __align__(16) h2x4 { __half2 a, b, c, d; };

// ---------------------------------------------------------------------------
// Scratch (device globals — no allocation allowed)
// ---------------------------------------------------------------------------
__device__ __half g_q [(size_t)MROWS * DWM];     // Q in half (GEMM epilogue out)
__device__ __half g_k [(size_t)MROWS * DWM];
__device__ __half g_v [(size_t)MROWS * DWM];
__device__ __half g_o [(size_t)MROWS * DWM];     // attention out (half)
__device__ __half g_xh[(size_t)MROWS * DWM];     // x in half
__device__ __half g_w [(size_t)4 * 1024 * 1024]; // 4 weights [K,N], half
__device__ float  g_bias[4 * 1024];
__device__ int    g_start[BSZ * PP];

// ---------------------------------------------------------------------------
// Helpers (portable PTX only — compute_103 virtual arch, no tcgen05)
// ---------------------------------------------------------------------------
__device__ __forceinline__ uint32_t smem_u32(const void* p) {
    uint32_t a;
    asm("{ .reg .u64 t; cvta.to.shared.u64 t, %1; cvt.u32.u64 %0, t; }" : "=r"(a) : "l"(p));
    return a;
}
#define CP16(d, s)  asm volatile("cp.async.cg.shared.global [%0], [%1], 16;" :: "r"(d), "l"(s) : "memory")
#define CP_COMMIT() asm volatile("cp.async.commit_group;" ::: "memory")
#define CP_WAIT1()  asm volatile("cp.async.wait_group 1;" ::: "memory")

__device__ __forceinline__ void ldsm_x4(uint32_t& r0, uint32_t& r1, uint32_t& r2, uint32_t& r3,
                                        uint32_t addr) {
    asm volatile("ldmatrix.sync.aligned.m8n8.x4.shared.b16 {%0,%1,%2,%3}, [%4];"
                 : "=r"(r0), "=r"(r1), "=r"(r2), "=r"(r3) : "r"(addr));
}
__device__ __forceinline__ void ldsm_x4t(uint32_t& r0, uint32_t& r1, uint32_t& r2, uint32_t& r3,
                                         uint32_t addr) {
    asm volatile("ldmatrix.sync.aligned.m8n8.x4.trans.shared.b16 {%0,%1,%2,%3}, [%4];"
                 : "=r"(r0), "=r"(r1), "=r"(r2), "=r"(r3) : "r"(addr));
}
__device__ __forceinline__ void mma16816(float* c,
                                         uint32_t a0, uint32_t a1, uint32_t a2, uint32_t a3,
                                         uint32_t b0, uint32_t b1) {
    asm volatile("mma.sync.aligned.m16n8k16.row.col.f32.f16.f16.f32 "
                 "{%0,%1,%2,%3}, {%4,%5,%6,%7}, {%8,%9}, {%0,%1,%2,%3};"
                 : "+f"(c[0]), "+f"(c[1]), "+f"(c[2]), "+f"(c[3])
                 : "r"(a0), "r"(a1), "r"(a2), "r"(a3), "r"(b0), "r"(b1));
}

// ---------------------------------------------------------------------------
// Prep: reset-mask dtype probe + window start indices + bias copy
// ---------------------------------------------------------------------------
__global__ void prep_kernel(const unsigned char* __restrict__ reset_raw,
                            const float* __restrict__ bq, const float* __restrict__ bk,
                            const float* __restrict__ bv, const float* __restrict__ bo)
{
    __shared__ int s_ni, s_nf, s_any;
    if (threadIdx.x == 0) { s_ni = 0; s_nf = 0; s_any = 0; }
    __syncthreads();
    const unsigned int* w32 = (const unsigned int*)reset_raw;
    int ni = 0, nf = 0, any = 0;
    for (int i = threadIdx.x; i < 8192; i += blockDim.x) {   // 32768 bytes, safe all dtypes
        unsigned int v = w32[i];
        if (v != 0u) {
            any = 1;
            if (v != 1u)          ni = 1;
            if (v != 0x3f800000u) nf = 1;
        }
    }
    if (ni)  atomicOr(&s_ni, 1);
    if (nf)  atomicOr(&s_nf, 1);
    if (any) atomicOr(&s_any, 1);
    __syncthreads();
    int mode;
    if (!s_any)      mode = -1;
    else if (!s_ni)  mode = 1;
    else if (!s_nf)  mode = 2;
    else             mode = 0;

    for (int b = threadIdx.x; b < BSZ; b += blockDim.x) {
        int r = 0;
        for (int t = 0; t < PP; t++) {
            int idx = b * PP + t;
            bool reset = false;
            if (mode == 0)      reset = (reset_raw[idx] != 0);
            else if (mode > 0)  reset = (w32[idx] != 0u);
            if (reset) r = t;
            int s = t - (WIN - 1);
            if (s < r) s = r;
            if (s < 0) s = 0;
            g_start[idx] = s;
        }
    }
    for (int i = threadIdx.x; i < 1024; i += blockDim.x) {
        g_bias[i]        = bq[i];
        g_bias[1024 + i] = bk[i];
        g_bias[2048 + i] = bv[i];
        g_bias[3072 + i] = bo[i];
    }
}

// ---------------------------------------------------------------------------
// Convert x / weights to half (one RN rounding)
// ---------------------------------------------------------------------------
__global__ void conv_x_kernel(const float4* __restrict__ x)
{
    size_t i = (size_t)blockIdx.x * blockDim.x + threadIdx.x;
    float4 v = x[i];
    __half2 p0 = __floats2half2_rn(v.x, v.y);
    __half2 p1 = __floats2half2_rn(v.z, v.w);
    __half2* dst = reinterpret_cast<__half2*>(g_xh) + 2 * i;
    dst[0] = p0; dst[1] = p1;
}

__global__ void conv_w_kernel(const float4* __restrict__ W0, const float4* __restrict__ W1,
                              const float4* __restrict__ W2, const float4* __restrict__ W3)
{
    const float4* W = (blockIdx.y == 0) ? W0 : (blockIdx.y == 1) ? W1
                    : (blockIdx.y == 2) ? W2 : W3;
    size_t i = (size_t)blockIdx.x * blockDim.x + threadIdx.x;   // 0..262143
    float4 v = W[i];
    __half2 p0 = __floats2half2_rn(v.x, v.y);
    __half2 p1 = __floats2half2_rn(v.z, v.w);
    __half2* dst = reinterpret_cast<__half2*>(g_w) + (size_t)blockIdx.y * 524288 + 2 * i;
    dst[0] = p0; dst[1] = p1;
}

// ---------------------------------------------------------------------------
// Pipelined FP16 GEMM with raw ldmatrix + mma.sync.m16n8k16 (replaces wmma:
// 12 vectorized ldmatrix per warp-k-tile instead of ~96 scalar LDS — the
// LSU-issue stream was the measured bottleneck keeping tensor at ~53%).
// Block 128x128, K-tile 32, 3-stage cp.async ring, 8 warps 4Mx2N,
// warp tile 32x64, 2 CTAs/SM. Accumulation order identical to the wmma
// version (wmma m16n16k16 == 2 of these HMMAs) -> same numerics.
//   asel:  0 -> A = g_xh, 1 -> A = g_o
//   wbase: 0 for fused QKV (half out to g_q/g_k/g_v), 3 for output proj (f32)
// ---------------------------------------------------------------------------
#define GBK   32
#define LDAh  40            // halves: 32 + 8 pad (80B rows, 16B-aligned)
#define LDBh  136           // halves: 128 + 8 pad (272B rows, 16B-aligned)
#define STG_AH    (128 * LDAh)                    // 5120 halves
#define STG_B_OFF (STG_AH * 2)                    // 10240 bytes
#define STG_BYTES (STG_B_OFF + GBK * LDBh * 2)    // 18944 bytes
#define GSMEM (3 * STG_BYTES)                     // 56832 bytes (2 CTAs/SM)

__global__ __launch_bounds__(256, 2)
void gemm_fp16_kernel(float* __restrict__ Cext, int asel, int wbase)
{
    extern __shared__ char smemraw[];
    const uint32_t sb = smem_u32(smemraw);
    const int tid = threadIdx.x, warp = tid >> 5, lane = tid & 31;
    const int w  = wbase + (blockIdx.x >> 3);
    const int bn = blockIdx.x & 7;
    const int bm = blockIdx.y;
    const int wm = warp & 3;      // 4 warps along M (32 rows each)
    const int wn = warp >> 2;     // 2 warps along N (64 cols each)

    const __half* A  = asel ? g_o : g_xh;
    const __half* Bw = g_w + (size_t)w * 1048576 + bn * 128;
    __half* Ch = (w == 0) ? g_q : (w == 1) ? g_k : g_v;   // used when w<3
    const float* bias = g_bias + w * 1024;

    const __half* Ab = A + (size_t)bm * 128 * 1024;

    // Per-thread cp.async plan: 2 A-chunks + 2 B-chunks of 16B (8 halves)
    const __half* asrc[2]; const __half* bsrc[2];
    uint32_t aoff[2], boff[2];
#pragma unroll
    for (int i = 0; i < 2; i++) {
        int idx = tid + i * 256;   // 0..511
        {   // A tile: 128 rows x 32 halves (4 chunks/row)
            int r = idx >> 2, c = idx & 3;
            asrc[i] = Ab + (size_t)r * 1024 + c * 8;
            aoff[i] = (uint32_t)(r * LDAh + c * 8) * 2;
        }
        {   // B tile: 32 rows (K) x 128 halves (16 chunks/row)
            int r = idx >> 4, c = idx & 15;
            bsrc[i] = Bw + (size_t)r * 1024 + c * 8;
            boff[i] = STG_B_OFF + (uint32_t)(r * LDBh + c * 8) * 2;
        }
    }

    // ldmatrix per-lane address offsets (within a stage)
    // A (x4, no trans): lane -> row (lane&15) of warp tile, k-col group (lane>>4)*8
    const uint32_t a_lane_off =
        (uint32_t)((wm * 32 + (lane & 15)) * LDAh + (lane >> 4) * 8) * 2;
    // B (x4, trans): lane -> k-row (lane&15), n-col group (lane>>4)*8
    const uint32_t b_lane_off = STG_B_OFF +
        (uint32_t)((lane & 15) * LDBh + wn * 64 + (lane >> 4) * 8) * 2;

    float acc[2][8][4];   // [mi: m16][nf: n8][c0..c3]
#pragma unroll
    for (int mi = 0; mi < 2; mi++)
#pragma unroll
        for (int nf = 0; nf < 8; nf++)
#pragma unroll
            for (int c = 0; c < 4; c++)
                acc[mi][nf][c] = 0.0f;

    // Prologue: tiles 0,1 -> stages 0,1
#pragma unroll
    for (int t = 0; t < 2; t++) {
        uint32_t st = sb + t * STG_BYTES;
#pragma unroll
        for (int i = 0; i < 2; i++) CP16(st + aoff[i], asrc[i] + t * 32);
#pragma unroll
        for (int i = 0; i < 2; i++) CP16(st + boff[i], bsrc[i] + (size_t)t * 32 * 1024);
        CP_COMMIT();
    }

    int s = 0;
    for (int t = 0; t < 32; t++) {
        CP_WAIT1();            // tile t landed (this thread)
        __syncthreads();       // ...for all threads; licenses overwriting stage
                               // (t+2)%3 == (t-1)%3 (consumed last iteration)

        const uint32_t stg = sb + s * STG_BYTES;
        const uint32_t aA = stg + a_lane_off;
        const uint32_t aB = stg + b_lane_off;
#pragma unroll
        for (int kk = 0; kk < GBK; kk += 16) {
            uint32_t af[2][4], bf[4][4];
#pragma unroll
            for (int mi = 0; mi < 2; mi++)
                ldsm_x4(af[mi][0], af[mi][1], af[mi][2], af[mi][3],
                        aA + (uint32_t)(mi * 16 * LDAh + kk) * 2);
#pragma unroll
            for (int np = 0; np < 4; np++)
                ldsm_x4t(bf[np][0], bf[np][1], bf[np][2], bf[np][3],
                         aB + (uint32_t)(kk * LDBh + np * 16) * 2);
#pragma unroll
            for (int mi = 0; mi < 2; mi++)
#pragma unroll
                for (int np = 0; np < 4; np++) {
                    mma16816(acc[mi][np * 2 + 0], af[mi][0], af[mi][1], af[mi][2], af[mi][3],
                             bf[np][0], bf[np][1]);
                    mma16816(acc[mi][np * 2 + 1], af[mi][0], af[mi][1], af[mi][2], af[mi][3],
                             bf[np][2], bf[np][3]);
                }
        }

        // Prefetch tile t+2 into stage (t+2)%3
        const int tp = t + 2;
        if (tp < 32) {
            int sp = s + 2; if (sp >= 3) sp -= 3;
            uint32_t st = sb + sp * STG_BYTES;
#pragma unroll
            for (int i = 0; i < 2; i++) CP16(st + aoff[i], asrc[i] + tp * 32);
#pragma unroll
            for (int i = 0; i < 2; i++) CP16(st + boff[i], bsrc[i] + (size_t)tp * 32 * 1024);
        }
        CP_COMMIT();

        if (++s == 3) s = 0;
    }
    __syncthreads();   // protect smem scratch reuse below

    // Epilogue: per-warp 16x20 scratch roundtrip (f32), bias add,
    // half (internal QKV) or float (final y) vectorized stores.
    // mma C frag layout: c0,c1 at (row lane/4, col 2*(lane%4)+{0,1}),
    //                    c2,c3 at (row lane/4+8, same cols).
    float* myC = (float*)smemraw + warp * 16 * 20;
    const int rr = lane >> 2;          // 0..7
    const int cc = (lane & 3) * 2;     // 0,2,4,6
    const int r  = lane >> 1;          // readback row
    const int ch = (lane & 1) * 8;     // readback col group
    const bool outHalf = (w < 3);
#pragma unroll
    for (int mi = 0; mi < 2; mi++)
#pragma unroll
        for (int ni = 0; ni < 4; ni++) {          // 16-col output groups
#pragma unroll
            for (int hf = 0; hf < 2; hf++) {      // two n8 frags per group
                const float* cfr = acc[mi][ni * 2 + hf];
                myC[rr * 20 + hf * 8 + cc]            = cfr[0];
                myC[rr * 20 + hf * 8 + cc + 1]        = cfr[1];
                myC[(rr + 8) * 20 + hf * 8 + cc]      = cfr[2];
                myC[(rr + 8) * 20 + hf * 8 + cc + 1]  = cfr[3];
            }
            __syncwarp();
            int gm = bm * 128 + wm * 32 + mi * 16 + r;
            int gn = bn * 128 + wn * 64 + ni * 16 + ch;
            float c0 = myC[r * 20 + ch + 0] + bias[gn + 0];
            float c1 = myC[r * 20 + ch + 1] + bias[gn + 1];
            float c2 = myC[r * 20 + ch + 2] + bias[gn + 2];
            float c3 = myC[r * 20 + ch + 3] + bias[gn + 3];
            float c4 = myC[r * 20 + ch + 4] + bias[gn + 4];
            float c5 = myC[r * 20 + ch + 5] + bias[gn + 5];
            float c6 = myC[r * 20 + ch + 6] + bias[gn + 6];
            float c7 = myC[r * 20 + ch + 7] + bias[gn + 7];
            if (outHalf) {
                h2x4 pk;
                pk.a = __floats2half2_rn(c0, c1);
                pk.b = __floats2half2_rn(c2, c3);
                pk.c = __floats2half2_rn(c4, c5);
                pk.d = __floats2half2_rn(c6, c7);
                *(h2x4*)(Ch + (size_t)gm * 1024 + gn) = pk;
            } else {
                *(float4*)(Cext + (size_t)gm * 1024 + gn)     = make_float4(c0, c1, c2, c3);
                *(float4*)(Cext + (size_t)gm * 1024 + gn + 4) = make_float4(c4, c5, c6, c7);
            }
            __syncwarp();
        }
}

// ---------------------------------------------------------------------------
// Sliding-window attention, max-free softmax (scores provably bounded ~|3.3|).
// Block = (batch b, tile of TQ=8 queries). Warp w owns heads 2w,2w+1;
// 16 lanes/head, 4 head-dims/lane. Half Q/K/V, fp32 math, half out.
// ---------------------------------------------------------------------------
__global__ __launch_bounds__(256)
void attn_kernel()
{
    const int b    = blockIdx.x;
    const int tb   = blockIdx.y * TQ;
    const int warp = threadIdx.x >> 5;
    const int lane = threadIdx.x & 31;
    const int h    = warp * 2 + (lane >> 4);
    const int sub  = lane & 15;
    const int d0   = h * 64 + sub * 4;

    const __half* qb = g_q + (size_t)b * PP * DWM;
    const __half* kb = g_k + (size_t)b * PP * DWM;
    const __half* vb = g_v + (size_t)b * PP * DWM;
    __half*       ob = g_o + (size_t)b * PP * DWM;

    float4 q4[TQ], acc[TQ];
    float  l[TQ];
    int    st[TQ];
#pragma unroll
    for (int i = 0; i < TQ; i++) {
        int t = tb + i;
        const __half2* qp = (const __half2*)(qb + (size_t)t * DWM + d0);
        float2 f0 = __half22float2(qp[0]);
        float2 f1 = __half22float2(qp[1]);
        q4[i]  = make_float4(f0.x, f0.y, f1.x, f1.y);
        st[i]  = g_start[b * PP + t];
        l[i]   = 0.0f;
        acc[i] = make_float4(0.f, 0.f, 0.f, 0.f);
    }

    const int jmin = st[0];            // start index monotone in t
    const int jmax = tb + TQ - 1;

    for (int j = jmin; j <= jmax; j++) {
        const __half2* kp = (const __half2*)(kb + (size_t)j * DWM + d0);
        const __half2* vp = (const __half2*)(vb + (size_t)j * DWM + d0);
        float2 k0 = __half22float2(kp[0]), k1 = __half22float2(kp[1]);
        float2 v0 = __half22float2(vp[0]), v1 = __half22float2(vp[1]);
        float4 k4 = make_float4(k0.x, k0.y, k1.x, k1.y);
        float4 v4 = make_float4(v0.x, v0.y, v1.x, v1.y);
        float s[TQ];
#pragma unroll
        for (int i = 0; i < TQ; i++)
            s[i] = q4[i].x * k4.x + q4[i].y * k4.y + q4[i].z * k4.z + q4[i].w * k4.w;
#pragma unroll
        for (int off = 8; off >= 1; off >>= 1)
#pragma unroll
            for (int i = 0; i < TQ; i++)
                s[i] += __shfl_xor_sync(0xffffffffu, s[i], off, 16);

#pragma unroll
        for (int i = 0; i < TQ; i++) {
            int t = tb + i;
            if (j >= st[i] && j <= t) {        // uniform across the warp
                float wt = __expf(s[i] * 0.125f);
                l[i] += wt;
                acc[i].x += wt * v4.x;
                acc[i].y += wt * v4.y;
                acc[i].z += wt * v4.z;
                acc[i].w += wt * v4.w;
            }
        }
    }

#pragma unroll
    for (int i = 0; i < TQ; i++) {
        float inv = 1.0f / l[i];
        __half2 p0 = __floats2half2_rn(acc[i].x * inv, acc[i].y * inv);
        __half2 p1 = __floats2half2_rn(acc[i].z * inv, acc[i].w * inv);
        __half2* dst = (__half2*)(ob + (size_t)(tb + i) * DWM + d0);
        dst[0] = p0; dst[1] = p1;
    }
}

// ---------------------------------------------------------------------------
// Launch
// ---------------------------------------------------------------------------
extern "C" void kernel_launch(void* const* d_in, const int* in_sizes, int n_in,
                              void* d_out, int out_size)
{
    const float*         x  = (const float*)d_in[0];
    const unsigned char* rs = (const unsigned char*)d_in[1];
    const float* Wq = (const float*)d_in[2];
    const float* bq = (const float*)d_in[3];
    const float* Wk = (const float*)d_in[4];
    const float* bk = (const float*)d_in[5];
    const float* Wv = (const float*)d_in[6];
    const float* bv = (const float*)d_in[7];
    const float* Wo = (const float*)d_in[8];
    const float* bo = (const float*)d_in[9];
    float* y = (float*)d_out;

    cudaFuncSetAttribute(gemm_fp16_kernel,
                         cudaFuncAttributeMaxDynamicSharedMemorySize, GSMEM);

    prep_kernel<<<1, 256>>>(rs, bq, bk, bv, bo);
    conv_x_kernel<<<32768, 256>>>((const float4*)x);
    conv_w_kernel<<<dim3(1024, 4), 256>>>((const float4*)Wq, (const float4*)Wk,
                                          (const float4*)Wv, (const float4*)Wo);

    // Fused Q,K,V projections: grid.x = 3 weights * 8 bn, grid.y = 32768/128
    gemm_fp16_kernel<<<dim3(24, 256), 256, GSMEM>>>(nullptr, 0, 0);

    attn_kernel<<<dim3(BSZ, PP / TQ), 256>>>();

    // y = attn_out @ Wo + bo (f32 out)
    gemm_fp16_kernel<<<dim3(8, 256), 256, GSMEM>>>(y, 1, 3);
}

// round 15
// speedup vs baseline: 1.1266x; 1.1266x over previous
#include <cuda_runtime.h>
#include <cuda_fp16.h>
#include <mma.h>
#include <cstdint>

using namespace nvcuda;

// Problem constants
#define BSZ   64
#define PP    512
#define DWM   1024
#define WIN   128
#define MROWS (BSZ * PP)   // 32768
#define TQ    8

// 16-byte vector of 8 halves for single-STG.128 stores
struct __align__(16) h2x4 { __half2 a, b, c, d; };

// ---------------------------------------------------------------------------
// Scratch (device globals — no allocation allowed)
// ---------------------------------------------------------------------------
__device__ __half g_q [(size_t)MROWS * DWM];     // Q in half (GEMM epilogue out)
__device__ __half g_k [(size_t)MROWS * DWM];
__device__ __half g_v [(size_t)MROWS * DWM];
__device__ __half g_o [(size_t)MROWS * DWM];     // attention out (half)
__device__ __half g_xh[(size_t)MROWS * DWM];     // x in half
__device__ __half g_w [(size_t)4 * 1024 * 1024]; // 4 weights [K,N], half
__device__ float  g_bias[4 * 1024];
__device__ int    g_start[BSZ * PP];

// ---------------------------------------------------------------------------
// Helpers (portable PTX only — compute_103 virtual arch, no tcgen05)
// ---------------------------------------------------------------------------
__device__ __forceinline__ uint32_t smem_u32(const void* p) {
    uint32_t a;
    asm("{ .reg .u64 t; cvta.to.shared.u64 t, %1; cvt.u32.u64 %0, t; }" : "=r"(a) : "l"(p));
    return a;
}
#define CP16(d, s)  asm volatile("cp.async.cg.shared.global [%0], [%1], 16;" :: "r"(d), "l"(s) : "memory")
#define CP_COMMIT() asm volatile("cp.async.commit_group;" ::: "memory")
#define CP_WAIT1()  asm volatile("cp.async.wait_group 1;" ::: "memory")

// ---------------------------------------------------------------------------
// Prep: reset-mask dtype probe + window start indices + bias copy
// ---------------------------------------------------------------------------
__global__ void prep_kernel(const unsigned char* __restrict__ reset_raw,
                            const float* __restrict__ bq, const float* __restrict__ bk,
                            const float* __restrict__ bv, const float* __restrict__ bo)
{
    __shared__ int s_ni, s_nf, s_any;
    if (threadIdx.x == 0) { s_ni = 0; s_nf = 0; s_any = 0; }
    __syncthreads();
    const unsigned int* w32 = (const unsigned int*)reset_raw;
    int ni = 0, nf = 0, any = 0;
    for (int i = threadIdx.x; i < 8192; i += blockDim.x) {   // 32768 bytes, safe all dtypes
        unsigned int v = w32[i];
        if (v != 0u) {
            any = 1;
            if (v != 1u)          ni = 1;
            if (v != 0x3f800000u) nf = 1;
        }
    }
    if (ni)  atomicOr(&s_ni, 1);
    if (nf)  atomicOr(&s_nf, 1);
    if (any) atomicOr(&s_any, 1);
    __syncthreads();
    int mode;
    if (!s_any)      mode = -1;
    else if (!s_ni)  mode = 1;
    else if (!s_nf)  mode = 2;
    else             mode = 0;

    for (int b = threadIdx.x; b < BSZ; b += blockDim.x) {
        int r = 0;
        for (int t = 0; t < PP; t++) {
            int idx = b * PP + t;
            bool reset = false;
            if (mode == 0)      reset = (reset_raw[idx] != 0);
            else if (mode > 0)  reset = (w32[idx] != 0u);
            if (reset) r = t;
            int s = t - (WIN - 1);
            if (s < r) s = r;
            if (s < 0) s = 0;
            g_start[idx] = s;
        }
    }
    for (int i = threadIdx.x; i < 1024; i += blockDim.x) {
        g_bias[i]        = bq[i];
        g_bias[1024 + i] = bk[i];
        g_bias[2048 + i] = bv[i];
        g_bias[3072 + i] = bo[i];
    }
}

// ---------------------------------------------------------------------------
// Convert x / weights to half (one RN rounding)
// ---------------------------------------------------------------------------
__global__ void conv_x_kernel(const float4* __restrict__ x)
{
    size_t i = (size_t)blockIdx.x * blockDim.x + threadIdx.x;
    float4 v = x[i];
    __half2 p0 = __floats2half2_rn(v.x, v.y);
    __half2 p1 = __floats2half2_rn(v.z, v.w);
    __half2* dst = reinterpret_cast<__half2*>(g_xh) + 2 * i;
    dst[0] = p0; dst[1] = p1;
}

__global__ void conv_w_kernel(const float4* __restrict__ W0, const float4* __restrict__ W1,
                              const float4* __restrict__ W2, const float4* __restrict__ W3)
{
    const float4* W = (blockIdx.y == 0) ? W0 : (blockIdx.y == 1) ? W1
                    : (blockIdx.y == 2) ? W2 : W3;
    size_t i = (size_t)blockIdx.x * blockDim.x + threadIdx.x;   // 0..262143
    float4 v = W[i];
    __half2 p0 = __floats2half2_rn(v.x, v.y);
    __half2 p1 = __floats2half2_rn(v.z, v.w);
    __half2* dst = reinterpret_cast<__half2*>(g_w) + (size_t)blockIdx.y * 524288 + 2 * i;
    dst[0] = p0; dst[1] = p1;
}

// ---------------------------------------------------------------------------
// Pipelined FP16 WMMA GEMM (proven R13 config — measured 676us QKV / 225us
// proj; smem-crossbar/tensor co-bound, at its local optimum for this ISA).
// Block 128x128, K-tile 32, 3-stage cp.async ring, 8 warps 4Mx2N,
// warp tile 32x64, 2 CTAs/SM.
//   asel:  0 -> A = g_xh, 1 -> A = g_o
//   wbase: 0 for fused QKV (half out to g_q/g_k/g_v), 3 for output proj (f32)
// ---------------------------------------------------------------------------
#define GBK   32
#define LDAh  40            // halves: 32 + 8 pad (80B rows)
#define LDBh  136           // halves: 128 + 8 pad (272B rows)
#define STG_AH    (128 * LDAh)                    // 5120 halves
#define STG_B_OFF (STG_AH * 2)                    // 10240 bytes
#define STG_BYTES (STG_B_OFF + GBK * LDBh * 2)    // 18944 bytes
#define GSMEM (3 * STG_BYTES)                     // 56832 bytes (2 CTAs/SM)

__global__ __launch_bounds__(256, 2)
void gemm_fp16_kernel(float* __restrict__ Cext, int asel, int wbase)
{
    extern __shared__ char smemraw[];
    const uint32_t sb = smem_u32(smemraw);
    const int tid = threadIdx.x, warp = tid >> 5, lane = tid & 31;
    const int w  = wbase + (blockIdx.x >> 3);
    const int bn = blockIdx.x & 7;
    const int bm = blockIdx.y;
    const int wm = warp & 3;      // 4 warps along M
    const int wn = warp >> 2;     // 2 warps along N

    const __half* A  = asel ? g_o : g_xh;
    const __half* Bw = g_w + (size_t)w * 1048576 + bn * 128;
    __half* Ch = (w == 0) ? g_q : (w == 1) ? g_k : g_v;   // used when w<3
    const float* bias = g_bias + w * 1024;

    const __half* Ab = A + (size_t)bm * 128 * 1024;

    // Per-thread cp.async plan: 2 A-chunks + 2 B-chunks of 16B (8 halves)
    const __half* asrc[2]; const __half* bsrc[2];
    uint32_t aoff[2], boff[2];
#pragma unroll
    for (int i = 0; i < 2; i++) {
        int idx = tid + i * 256;   // 0..511
        {   // A tile: 128 rows x 32 halves (4 chunks/row)
            int r = idx >> 2, c = idx & 3;
            asrc[i] = Ab + (size_t)r * 1024 + c * 8;
            aoff[i] = (uint32_t)(r * LDAh + c * 8) * 2;
        }
        {   // B tile: 32 rows (K) x 128 halves (16 chunks/row)
            int r = idx >> 4, c = idx & 15;
            bsrc[i] = Bw + (size_t)r * 1024 + c * 8;
            boff[i] = STG_B_OFF + (uint32_t)(r * LDBh + c * 8) * 2;
        }
    }

    wmma::fragment<wmma::accumulator, 16, 16, 16, float> acc[2][4];
#pragma unroll
    for (int mi = 0; mi < 2; mi++)
#pragma unroll
        for (int ni = 0; ni < 4; ni++)
            wmma::fill_fragment(acc[mi][ni], 0.0f);

    // Prologue: tiles 0,1 -> stages 0,1
#pragma unroll
    for (int t = 0; t < 2; t++) {
        uint32_t st = sb + t * STG_BYTES;
#pragma unroll
        for (int i = 0; i < 2; i++) CP16(st + aoff[i], asrc[i] + t * 32);
#pragma unroll
        for (int i = 0; i < 2; i++) CP16(st + boff[i], bsrc[i] + (size_t)t * 32 * 1024);
        CP_COMMIT();
    }

    int s = 0;
    for (int t = 0; t < 32; t++) {
        CP_WAIT1();            // tile t landed (this thread)
        __syncthreads();       // ...for all threads; licenses overwriting stage
                               // (t+2)%3 == (t-1)%3 (consumed last iteration)

        const __half* sA  = (const __half*)(smemraw + s * STG_BYTES);
        const __half* sBt = (const __half*)(smemraw + s * STG_BYTES + STG_B_OFF);
#pragma unroll
        for (int kk = 0; kk < GBK; kk += 16) {
            wmma::fragment<wmma::matrix_a, 16, 16, 16, __half, wmma::row_major> af[2];
            wmma::fragment<wmma::matrix_b, 16, 16, 16, __half, wmma::row_major> bf[4];
#pragma unroll
            for (int mi = 0; mi < 2; mi++)
                wmma::load_matrix_sync(af[mi], sA + (wm * 32 + mi * 16) * LDAh + kk, LDAh);
#pragma unroll
            for (int ni = 0; ni < 4; ni++)
                wmma::load_matrix_sync(bf[ni], sBt + kk * LDBh + wn * 64 + ni * 16, LDBh);
#pragma unroll
            for (int mi = 0; mi < 2; mi++)
#pragma unroll
                for (int ni = 0; ni < 4; ni++)
                    wmma::mma_sync(acc[mi][ni], af[mi], bf[ni], acc[mi][ni]);
        }

        // Prefetch tile t+2 into stage (t+2)%3
        const int tp = t + 2;
        if (tp < 32) {
            int sp = s + 2; if (sp >= 3) sp -= 3;
            uint32_t st = sb + sp * STG_BYTES;
#pragma unroll
            for (int i = 0; i < 2; i++) CP16(st + aoff[i], asrc[i] + tp * 32);
#pragma unroll
            for (int i = 0; i < 2; i++) CP16(st + boff[i], bsrc[i] + (size_t)tp * 32 * 1024);
        }
        CP_COMMIT();

        if (++s == 3) s = 0;
    }
    __syncthreads();   // protect smem scratch reuse below

    // Epilogue: per-warp 16x20 scratch roundtrip (f32), bias add,
    // half (internal QKV) or float (final y) vectorized stores.
    float* myC = (float*)smemraw + warp * 16 * 20;
    const int r  = lane >> 1;
    const int ch = (lane & 1) * 8;
    const bool outHalf = (w < 3);
#pragma unroll
    for (int mi = 0; mi < 2; mi++)
#pragma unroll
        for (int ni = 0; ni < 4; ni++) {
            wmma::store_matrix_sync(myC, acc[mi][ni], 20, wmma::mem_row_major);
            __syncwarp();
            int gm = bm * 128 + wm * 32 + mi * 16 + r;
            int gn = bn * 128 + wn * 64 + ni * 16 + ch;
            float c0 = myC[r * 20 + ch + 0] + bias[gn + 0];
            float c1 = myC[r * 20 + ch + 1] + bias[gn + 1];
            float c2 = myC[r * 20 + ch + 2] + bias[gn + 2];
            float c3 = myC[r * 20 + ch + 3] + bias[gn + 3];
            float c4 = myC[r * 20 + ch + 4] + bias[gn + 4];
            float c5 = myC[r * 20 + ch + 5] + bias[gn + 5];
            float c6 = myC[r * 20 + ch + 6] + bias[gn + 6];
            float c7 = myC[r * 20 + ch + 7] + bias[gn + 7];
            if (outHalf) {
                h2x4 pk;
                pk.a = __floats2half2_rn(c0, c1);
                pk.b = __floats2half2_rn(c2, c3);
                pk.c = __floats2half2_rn(c4, c5);
                pk.d = __floats2half2_rn(c6, c7);
                *(h2x4*)(Ch + (size_t)gm * 1024 + gn) = pk;
            } else {
                *(float4*)(Cext + (size_t)gm * 1024 + gn)     = make_float4(c0, c1, c2, c3);
                *(float4*)(Cext + (size_t)gm * 1024 + gn + 4) = make_float4(c4, c5, c6, c7);
            }
            __syncwarp();
        }
}

// ---------------------------------------------------------------------------
// Sliding-window attention, max-free softmax, j-loop UNROLLED x2:
// 8 independent loads in flight (MLP 4->8) and two independent 4-deep shfl
// reduction trees interleaved (ILP 2 on the ~104-cyc chain) — attacks the
// measured latency bound. Updates applied j then j+1 sequentially ->
// accumulation order identical to the unrolled-by-1 version (bitwise same).
// q pre-scaled by 0.125 (exact power of 2 -> bitwise-identical scores).
// Block = (batch b, tile of TQ=8 queries). Warp w owns heads 2w,2w+1;
// 16 lanes/head, 4 head-dims/lane. Half Q/K/V, fp32 math, half out.
// ---------------------------------------------------------------------------
__global__ __launch_bounds__(256)
void attn_kernel()
{
    const int b    = blockIdx.x;
    const int tb   = blockIdx.y * TQ;
    const int warp = threadIdx.x >> 5;
    const int lane = threadIdx.x & 31;
    const int h    = warp * 2 + (lane >> 4);
    const int sub  = lane & 15;
    const int d0   = h * 64 + sub * 4;

    const __half* qb = g_q + (size_t)b * PP * DWM;
    const __half* kb = g_k + (size_t)b * PP * DWM;
    const __half* vb = g_v + (size_t)b * PP * DWM;
    __half*       ob = g_o + (size_t)b * PP * DWM;

    float4 q4[TQ], acc[TQ];
    float  l[TQ];
    int    st[TQ];
#pragma unroll
    for (int i = 0; i < TQ; i++) {
        int t = tb + i;
        const __half2* qp = (const __half2*)(qb + (size_t)t * DWM + d0);
        float2 f0 = __half22float2(qp[0]);
        float2 f1 = __half22float2(qp[1]);
        // pre-scale by 1/sqrt(64)=0.125 (exact) -> drops one FMUL per (i,j)
        q4[i]  = make_float4(f0.x * 0.125f, f0.y * 0.125f,
                             f1.x * 0.125f, f1.y * 0.125f);
        st[i]  = g_start[b * PP + t];
        l[i]   = 0.0f;
        acc[i] = make_float4(0.f, 0.f, 0.f, 0.f);
    }

    const int jmin = st[0];            // start index monotone in t
    const int jmax = tb + TQ - 1;

    int j = jmin;
    for (; j + 1 <= jmax; j += 2) {
        // ---- load both rows up front (8 independent LDG.64) ----
        const __half2* kp0 = (const __half2*)(kb + (size_t)j * DWM + d0);
        const __half2* vp0 = (const __half2*)(vb + (size_t)j * DWM + d0);
        const __half2* kp1 = (const __half2*)(kb + (size_t)(j + 1) * DWM + d0);
        const __half2* vp1 = (const __half2*)(vb + (size_t)(j + 1) * DWM + d0);
        __half2 ka0 = kp0[0], kb0 = kp0[1], va0 = vp0[0], vb0 = vp0[1];
        __half2 ka1 = kp1[0], kb1 = kp1[1], va1 = vp1[0], vb1 = vp1[1];

        float2 k00 = __half22float2(ka0), k01 = __half22float2(kb0);
        float2 k10 = __half22float2(ka1), k11 = __half22float2(kb1);
        float2 v00 = __half22float2(va0), v01 = __half22float2(vb0);
        float2 v10 = __half22float2(va1), v11 = __half22float2(vb1);
        float4 k4a = make_float4(k00.x, k00.y, k01.x, k01.y);
        float4 k4b = make_float4(k10.x, k10.y, k11.x, k11.y);
        float4 v4a = make_float4(v00.x, v00.y, v01.x, v01.y);
        float4 v4b = make_float4(v10.x, v10.y, v11.x, v11.y);

        // ---- two independent dot sets ----
        float s0[TQ], s1[TQ];
#pragma unroll
        for (int i = 0; i < TQ; i++) {
            s0[i] = q4[i].x * k4a.x + q4[i].y * k4a.y + q4[i].z * k4a.z + q4[i].w * k4a.w;
            s1[i] = q4[i].x * k4b.x + q4[i].y * k4b.y + q4[i].z * k4b.z + q4[i].w * k4b.w;
        }
        // ---- interleaved reduction trees (ILP 2 on the shfl chain) ----
#pragma unroll
        for (int off = 8; off >= 1; off >>= 1) {
#pragma unroll
            for (int i = 0; i < TQ; i++) {
                s0[i] += __shfl_xor_sync(0xffffffffu, s0[i], off, 16);
                s1[i] += __shfl_xor_sync(0xffffffffu, s1[i], off, 16);
            }
        }

        // ---- updates, j first then j+1 (same order as unrolled-by-1) ----
#pragma unroll
        for (int i = 0; i < TQ; i++) {
            int t = tb + i;
            if (j >= st[i] && j <= t) {
                float wt = __expf(s0[i]);
                l[i] += wt;
                acc[i].x += wt * v4a.x;
                acc[i].y += wt * v4a.y;
                acc[i].z += wt * v4a.z;
                acc[i].w += wt * v4a.w;
            }
        }
#pragma unroll
        for (int i = 0; i < TQ; i++) {
            int t = tb + i;
            if (j + 1 >= st[i] && j + 1 <= t) {
                float wt = __expf(s1[i]);
                l[i] += wt;
                acc[i].x += wt * v4b.x;
                acc[i].y += wt * v4b.y;
                acc[i].z += wt * v4b.z;
                acc[i].w += wt * v4b.w;
            }
        }
    }

    // ---- odd tail ----
    if (j <= jmax) {
        const __half2* kp = (const __half2*)(kb + (size_t)j * DWM + d0);
        const __half2* vp = (const __half2*)(vb + (size_t)j * DWM + d0);
        float2 k0 = __half22float2(kp[0]), k1 = __half22float2(kp[1]);
        float2 v0 = __half22float2(vp[0]), v1 = __half22float2(vp[1]);
        float4 k4 = make_float4(k0.x, k0.y, k1.x, k1.y);
        float4 v4 = make_float4(v0.x, v0.y, v1.x, v1.y);
        float s[TQ];
#pragma unroll
        for (int i = 0; i < TQ; i++)
            s[i] = q4[i].x * k4.x + q4[i].y * k4.y + q4[i].z * k4.z + q4[i].w * k4.w;
#pragma unroll
        for (int off = 8; off >= 1; off >>= 1)
#pragma unroll
            for (int i = 0; i < TQ; i++)
                s[i] += __shfl_xor_sync(0xffffffffu, s[i], off, 16);
#pragma unroll
        for (int i = 0; i < TQ; i++) {
            int t = tb + i;
            if (j >= st[i] && j <= t) {
                float wt = __expf(s[i]);
                l[i] += wt;
                acc[i].x += wt * v4.x;
                acc[i].y += wt * v4.y;
                acc[i].z += wt * v4.z;
                acc[i].w += wt * v4.w;
            }
        }
    }

#pragma unroll
    for (int i = 0; i < TQ; i++) {
        float inv = 1.0f / l[i];
        __half2 p0 = __floats2half2_rn(acc[i].x * inv, acc[i].y * inv);
        __half2 p1 = __floats2half2_rn(acc[i].z * inv, acc[i].w * inv);
        __half2* dst = (__half2*)(ob + (size_t)(tb + i) * DWM + d0);
        dst[0] = p0; dst[1] = p1;
    }
}

// ---------------------------------------------------------------------------
// Launch
// ---------------------------------------------------------------------------
extern "C" void kernel_launch(void* const* d_in, const int* in_sizes, int n_in,
                              void* d_out, int out_size)
{
    const float*         x  = (const float*)d_in[0];
    const unsigned char* rs = (const unsigned char*)d_in[1];
    const float* Wq = (const float*)d_in[2];
    const float* bq = (const float*)d_in[3];
    const float* Wk = (const float*)d_in[4];
    const float* bk = (const float*)d_in[5];
    const float* Wv = (const float*)d_in[6];
    const float* bv = (const float*)d_in[7];
    const float* Wo = (const float*)d_in[8];
    const float* bo = (const float*)d_in[9];
    float* y = (float*)d_out;

    cudaFuncSetAttribute(gemm_fp16_kernel,
                         cudaFuncAttributeMaxDynamicSharedMemorySize, GSMEM);

    prep_kernel<<<1, 256>>>(rs, bq, bk, bv, bo);
    conv_x_kernel<<<32768, 256>>>((const float4*)x);
    conv_w_kernel<<<dim3(1024, 4), 256>>>((const float4*)Wq, (const float4*)Wk,
                                          (const float4*)Wv, (const float4*)Wo);

    // Fused Q,K,V projections: grid.x = 3 weights * 8 bn, grid.y = 32768/128
    gemm_fp16_kernel<<<dim3(24, 256), 256, GSMEM>>>(nullptr, 0, 0);

    attn_kernel<<<dim3(BSZ, PP / TQ), 256>>>();

    // y = attn_out @ Wo + bo (f32 out)
    gemm_fp16_kernel<<<dim3(8, 256), 256, GSMEM>>>(y, 1, 3);
}